// round 7
// baseline (speedup 1.0000x reference)
#include <cuda_runtime.h>
#include <math.h>
#include <stdint.h>

#define N_   32
#define C_   512
#define HW_  4096          // 64*64
#define D_   4
#define BLK_ 128           // C_/D_
#define HID_ 32            // C_/16
#define CD_  (C_ * D_)     // 2048

// ---- scratch (no allocations allowed) ----
__device__ float g_avgp[N_ * C_];
__device__ float g_maxp[N_ * C_];
__device__ int   g_idx [N_ * C_];   // selected channels, output order

// ---------------------------------------------------------------------------
// K1: per-(n,c) avg + max pooling over HW_ elements. One block per row.
// (83.5% DRAM peak — at the roofline, leave alone.)
// ---------------------------------------------------------------------------
__global__ __launch_bounds__(256) void pool_kernel(const float* __restrict__ x) {
    const int row = blockIdx.x;                      // n*C + c
    const float4* xr = reinterpret_cast<const float4*>(x + (size_t)row * HW_);

    float s = 0.0f;
    float m = -INFINITY;
    #pragma unroll 4
    for (int i = threadIdx.x; i < HW_ / 4; i += 256) {
        float4 v = xr[i];
        s += (v.x + v.y) + (v.z + v.w);
        m = fmaxf(m, fmaxf(fmaxf(v.x, v.y), fmaxf(v.z, v.w)));
    }
    #pragma unroll
    for (int off = 16; off > 0; off >>= 1) {
        s += __shfl_xor_sync(0xffffffffu, s, off);
        m = fmaxf(m, __shfl_xor_sync(0xffffffffu, m, off));
    }
    __shared__ float ss[8], sm[8];
    const int wid = threadIdx.x >> 5;
    const int lid = threadIdx.x & 31;
    if (lid == 0) { ss[wid] = s; sm[wid] = m; }
    __syncthreads();
    if (threadIdx.x == 0) {
        float ts = ss[0], tm = sm[0];
        #pragma unroll
        for (int w = 1; w < 8; w++) { ts += ss[w]; tm = fmaxf(tm, sm[w]); }
        g_avgp[row] = ts * (1.0f / HW_);
        g_maxp[row] = tm;
    }
}

// ---------------------------------------------------------------------------
// K2: fused MLP + sigmoid + top-128 rank. One block per (n, d).
//   Layer 1 redundantly computed per d-block (cheap, coalesced).
//   Layer 2 computes only the 512 outputs o = c*4 + d this block ranks.
//   key = (bits(sigmoid) << 16) | (65535 - c): sigmoid > 0 so float bits are
//   monotone; lower-index tiebreak in the low bits. Rank-by-count = lax.top_k.
// ---------------------------------------------------------------------------
__global__ __launch_bounds__(512) void mlp_rank_kernel(
    const float* __restrict__ W1, const float* __restrict__ b1,
    const float* __restrict__ W2, const float* __restrict__ b2) {
    const int b   = blockIdx.x;      // n*D + d
    const int n   = b >> 2;
    const int d   = b & 3;
    const int tid = threadIdx.x;
    const int w   = tid >> 5;        // warp 0..15
    const int j   = tid & 31;        // lane = hidden index

    __shared__ float avg_s[C_];
    __shared__ float max_s[C_];
    __shared__ float part_a[16 * HID_];
    __shared__ float part_m[16 * HID_];
    __shared__ float hs[HID_];
    __shared__ unsigned long long keys[C_];

    avg_s[tid] = g_avgp[n * C_ + tid];
    max_s[tid] = g_maxp[n * C_ + tid];
    __syncthreads();

    // Layer 1, coalesced: warp w handles channels c = w, w+16, ...; lane j
    // reads W1[c][j] (one 128B line per warp per c).
    {
        float sa = 0.0f, smx = 0.0f;
        #pragma unroll 8
        for (int c = w; c < C_; c += 16) {
            float w1 = W1[c * HID_ + j];
            sa  = fmaf(avg_s[c], w1, sa);
            smx = fmaf(max_s[c], w1, smx);
        }
        part_a[w * HID_ + j] = sa;
        part_m[w * HID_ + j] = smx;
    }
    __syncthreads();
    if (tid < HID_) {
        float sa = 0.0f, smx = 0.0f;
        #pragma unroll
        for (int ww = 0; ww < 16; ww++) {
            sa  += part_a[ww * HID_ + tid];
            smx += part_m[ww * HID_ + tid];
        }
        float bb = b1[tid];
        hs[tid] = fmaxf(sa + bb, 0.0f) + fmaxf(smx + bb, 0.0f);
    }
    __syncthreads();

    // Layer 2 + sigmoid + key: thread c computes output o = c*4 + d.
    {
        const int c = tid;
        const int o = c * D_ + d;
        float acc = 2.0f * b2[o];
        #pragma unroll
        for (int k = 0; k < HID_; k++)
            acc = fmaf(hs[k], W2[k * CD_ + o], acc);
        float v = 1.0f / (1.0f + expf(-acc));
        keys[c] = ((unsigned long long)__float_as_uint(v) << 16) |
                  (unsigned long long)(65535 - c);
    }
    __syncthreads();

    // Rank by count: thread c counts keys strictly greater than its own.
    {
        const unsigned long long myk = keys[tid];
        int rank = 0;
        const ulonglong2* k2 = reinterpret_cast<const ulonglong2*>(keys);
        #pragma unroll 8
        for (int i = 0; i < C_ / 2; i++) {
            ulonglong2 u = k2[i];
            rank += (u.x > myk) + (u.y > myk);
        }
        if (rank < BLK_)
            g_idx[n * C_ + d * BLK_ + rank] = tid;
    }
}

// ---------------------------------------------------------------------------
// K3: gather — copy the selected channel planes. One block per output row.
// Reads cached (duplicate channels hit L2); writes streaming.
// ---------------------------------------------------------------------------
__global__ __launch_bounds__(256) void gather_kernel(
    const float* __restrict__ x, float* __restrict__ out) {
    const int row = blockIdx.x;              // n*512 + j
    const int n   = row >> 9;
    const int c   = g_idx[row];
    const float4* src = reinterpret_cast<const float4*>(
        x + ((size_t)n * C_ + c) * HW_);
    float4* dst = reinterpret_cast<float4*>(out + (size_t)row * HW_);
    #pragma unroll 4
    for (int i = threadIdx.x; i < HW_ / 4; i += 256) {
        float4 v = src[i];
        __stcs(dst + i, v);
    }
}

extern "C" void kernel_launch(void* const* d_in, const int* in_sizes, int n_in,
                              void* d_out, int out_size) {
    const float* x  = (const float*)d_in[0];
    const float* W1 = (const float*)d_in[1];
    const float* b1 = (const float*)d_in[2];
    const float* W2 = (const float*)d_in[3];
    const float* b2 = (const float*)d_in[4];
    float* out = (float*)d_out;

    pool_kernel<<<N_ * C_, 256>>>(x);
    mlp_rank_kernel<<<N_ * D_, 512>>>(W1, b1, W2, b2);
    gather_kernel<<<N_ * C_, 256>>>(x, out);
}